// round 1
// baseline (speedup 1.0000x reference)
#include <cuda_runtime.h>

#define LMAX 8
#define NSH  81   // (LMAX+1)^2
#define NF   45   // (LMAX+1)(LMAX+2)/2
#define TILE 128

__global__ __launch_bounds__(TILE)
void sh_kernel(const float* __restrict__ xyz,
               const float* __restrict__ F,
               float* __restrict__ out,
               int n)
{
    __shared__ __align__(16) float s_out[TILE * NSH];
    __shared__ float s_F[NF];

    const int tid = threadIdx.x;
    if (tid < NF) s_F[tid] = F[tid];
    __syncthreads();

    const int base_pt = blockIdx.x * TILE;
    const int p = base_pt + tid;

    if (p < n) {
        float x = xyz[3 * p + 0];
        float y = xyz[3 * p + 1];
        float z = xyz[3 * p + 2];
        const float rinv = rsqrtf(x * x + y * y + z * z);
        x *= rinv; y *= rinv; z *= rinv;

        // Associated-Legendre-style recurrence, flattened triangular Q[l*(l+1)/2 + m].
        // Fully unrolled -> constant indices -> registers.
        float Q[NF];
        Q[0] = 1.0f;
        #pragma unroll
        for (int l = 1; l <= LMAX; ++l) {
            const int b   = l * (l + 1) / 2;
            const int bp  = (l - 1) * l / 2;
            const int bpp = (l - 2) * (l - 1) / 2;  // unused when l==1
            Q[b + l]     = -(2.0f * l - 1.0f) * Q[bp + (l - 1)];
            Q[b + l - 1] = -z * Q[b + l];
            #pragma unroll
            for (int m = 0; m <= l - 2; ++m) {
                Q[b + m] = ((2.0f * l - 1.0f) * z * Q[bp + m]
                            - (float)(l + m - 1) * Q[bpp + m])
                           * (1.0f / (float)(l - m));
            }
        }

        float sv[LMAX + 1], cv[LMAX + 1];
        sv[0] = 0.0f; cv[0] = 1.0f;
        #pragma unroll
        for (int m = 1; m <= LMAX; ++m) {
            sv[m] = x * sv[m - 1] + y * cv[m - 1];
            cv[m] = x * cv[m - 1] - y * sv[m - 1];
        }

        const float inv_sqrt2 = 0.70710678118654752440f;
        // smem row writes: addr word = tid*81 + col; across a warp at fixed col the
        // bank is (17*tid + col) mod 32 -> permutation (17 odd) -> conflict-free.
        float* row = &s_out[tid * NSH];
        #pragma unroll
        for (int l = 0; l <= LMAX; ++l) {
            const int b  = l * (l + 1) / 2;
            const int cb = l * l;
            #pragma unroll
            for (int k = l; k >= 1; --k)        // m = -l .. -1  (k = -m)
                row[cb + l - k] = s_F[b + k] * Q[b + k] * sv[k];
            row[cb + l] = s_F[b] * Q[b] * inv_sqrt2;   // m = 0
            #pragma unroll
            for (int m = 1; m <= l; ++m)        // m = 1 .. l
                row[cb + l + m] = s_F[b + m] * Q[b + m] * cv[m];
        }
    }
    __syncthreads();

    // Cooperative coalesced copy-out. Tile base byte offset = blockIdx*TILE*81*4
    // = blockIdx * 41472, 16B-aligned -> float4 stores are legal.
    const int valid = min(TILE, n - base_pt);
    const long long gbase = (long long)base_pt * NSH;
    if (valid == TILE) {
        const float4* src = (const float4*)s_out;
        float4* dst = (float4*)(out + gbase);
        const int nvec = TILE * NSH / 4;  // 2592
        #pragma unroll 4
        for (int i = tid; i < nvec; i += TILE)
            dst[i] = src[i];
    } else if (valid > 0) {
        const int total = valid * NSH;
        for (int i = tid; i < total; i += TILE)
            out[gbase + i] = s_out[i];
    }
}

extern "C" void kernel_launch(void* const* d_in, const int* in_sizes, int n_in,
                              void* d_out, int out_size)
{
    const float* xyz = (const float*)d_in[0];
    const float* F   = (const float*)d_in[1];
    float* out       = (float*)d_out;
    const int n = in_sizes[0] / 3;
    const int grid = (n + TILE - 1) / TILE;
    sh_kernel<<<grid, TILE>>>(xyz, F, out, n);
}

// round 2
// speedup vs baseline: 1.0124x; 1.0124x over previous
#include <cuda_runtime.h>

#define LMAX  8
#define NSH   81   // (LMAX+1)^2
#define NF    45   // (LMAX+1)(LMAX+2)/2
#define TILE  128
#define CHUNK 16   // points staged per warp per phase
#define NWARP (TILE / 32)

__global__ __launch_bounds__(TILE)
void sh_kernel(const float* __restrict__ xyz,
               const float* __restrict__ F,
               float* __restrict__ out,
               int n)
{
    // Per-warp staging buffer: CHUNK points x 81 floats = 5184 B, 16B-aligned.
    __shared__ __align__(16) float s_out[NWARP * CHUNK * NSH];
    __shared__ float s_F[NF];

    const int tid  = threadIdx.x;
    const int lane = tid & 31;
    const int warp = tid >> 5;

    if (tid < NF) s_F[tid] = F[tid];
    __syncthreads();   // s_F visible to all warps (only block-wide barrier)

    const int base_pt = blockIdx.x * TILE;
    const int p       = base_pt + tid;

    // ---- compute Q (assoc. Legendre recurrence), sv/cv (azimuthal) ----
    float x = 0.0f, y = 0.0f, z = 1.0f;
    if (p < n) {
        x = xyz[3 * p + 0];
        y = xyz[3 * p + 1];
        z = xyz[3 * p + 2];
    }
    const float rinv = rsqrtf(x * x + y * y + z * z);
    x *= rinv; y *= rinv; z *= rinv;

    float Q[NF];
    Q[0] = 1.0f;
    #pragma unroll
    for (int l = 1; l <= LMAX; ++l) {
        const int b   = l * (l + 1) / 2;
        const int bp  = (l - 1) * l / 2;
        const int bpp = (l - 2) * (l - 1) / 2;   // unused when l==1
        Q[b + l]     = -(2.0f * l - 1.0f) * Q[bp + (l - 1)];
        Q[b + l - 1] = -z * Q[b + l];
        #pragma unroll
        for (int m = 0; m <= l - 2; ++m) {
            Q[b + m] = ((2.0f * l - 1.0f) * z * Q[bp + m]
                        - (float)(l + m - 1) * Q[bpp + m])
                       * (1.0f / (float)(l - m));
        }
    }

    float sv[LMAX + 1], cv[LMAX + 1];
    sv[0] = 0.0f; cv[0] = 1.0f;
    #pragma unroll
    for (int m = 1; m <= LMAX; ++m) {
        sv[m] = x * sv[m - 1] + y * cv[m - 1];
        cv[m] = x * cv[m - 1] - y * sv[m - 1];
    }

    const float inv_sqrt2 = 0.70710678118654752440f;
    float* const warp_buf = s_out + warp * (CHUNK * NSH);

    // ---- two phases: lanes [16h,16h+16) stage, whole warp copies out ----
    #pragma unroll
    for (int half = 0; half < 2; ++half) {
        const int chunk_base = base_pt + warp * 32 + half * CHUNK;

        if ((lane >> 4) == half && p < n) {
            // smem row stride 81 words: bank = (17*i + c) mod 32 over i=0..15
            // is a permutation (17 odd) -> conflict-free at fixed column c.
            float* row = warp_buf + (lane & 15) * NSH;
            #pragma unroll
            for (int l = 0; l <= LMAX; ++l) {
                const int b  = l * (l + 1) / 2;
                const int cb = l * l;
                #pragma unroll
                for (int k = l; k >= 1; --k)              // m = -l .. -1
                    row[cb + l - k] = s_F[b + k] * Q[b + k] * sv[k];
                row[cb + l] = s_F[b] * Q[b] * inv_sqrt2;  // m = 0
                #pragma unroll
                for (int m = 1; m <= l; ++m)              // m = 1 .. l
                    row[cb + l + m] = s_F[b + m] * Q[b + m] * cv[m];
            }
        }
        __syncwarp();

        const int valid = min(CHUNK, n - chunk_base);
        if (valid == CHUNK) {
            // Contiguous 16*81*4 = 5184 B chunk; base offset chunk_base*324 B
            // with chunk_base % 16 == 0 -> 16B-aligned float4 stores.
            float4* dst = (float4*)(out + (long long)chunk_base * NSH);
            const float4* src = (const float4*)warp_buf;
            #pragma unroll 4
            for (int i = lane; i < CHUNK * NSH / 4; i += 32)   // 324 vecs
                dst[i] = src[i];
        } else if (valid > 0) {
            const int total = valid * NSH;
            float* dst = out + (long long)chunk_base * NSH;
            for (int i = lane; i < total; i += 32)
                dst[i] = warp_buf[i];
        }
        __syncwarp();
    }
}

extern "C" void kernel_launch(void* const* d_in, const int* in_sizes, int n_in,
                              void* d_out, int out_size)
{
    const float* xyz = (const float*)d_in[0];
    const float* F   = (const float*)d_in[1];
    float* out       = (float*)d_out;
    const int n = in_sizes[0] / 3;
    const int grid = (n + TILE - 1) / TILE;
    sh_kernel<<<grid, TILE>>>(xyz, F, out, n);
}

// round 3
// speedup vs baseline: 1.0603x; 1.0473x over previous
#include <cuda_runtime.h>
#include <cstdint>

#define LMAX  8
#define NSH   81   // (LMAX+1)^2
#define NF    45   // (LMAX+1)(LMAX+2)/2
#define TILE  128
#define NWARP (TILE / 32)
#define CHUNK_BYTES (32 * NSH * 4)   // 10368 B per warp, %16 == 0

__global__ __launch_bounds__(TILE)
void sh_kernel(const float* __restrict__ xyz,
               const float* __restrict__ F,
               float* __restrict__ out,
               int n)
{
    // Per-warp staging: 32 points x 81 floats = 10368 B. Base 16B-aligned.
    __shared__ __align__(16) float s_out[NWARP * 32 * NSH];
    __shared__ float s_F[NF];

    const int tid  = threadIdx.x;
    const int lane = tid & 31;
    const int warp = tid >> 5;

    if (tid < NF) s_F[tid] = F[tid];
    __syncthreads();

    const int base_pt    = blockIdx.x * TILE;
    const int chunk_base = base_pt + warp * 32;
    const int p          = chunk_base + lane;

    float x = 0.0f, y = 0.0f, z = 1.0f;
    if (p < n) {
        x = xyz[3 * p + 0];
        y = xyz[3 * p + 1];
        z = xyz[3 * p + 2];
    }
    const float rinv = rsqrtf(x * x + y * y + z * z);
    x *= rinv; y *= rinv; z *= rinv;

    // Associated-Legendre recurrence, flattened triangular Q[l*(l+1)/2+m],
    // fully unrolled -> registers.
    float Q[NF];
    Q[0] = 1.0f;
    #pragma unroll
    for (int l = 1; l <= LMAX; ++l) {
        const int b   = l * (l + 1) / 2;
        const int bp  = (l - 1) * l / 2;
        const int bpp = (l - 2) * (l - 1) / 2;   // unused when l==1
        Q[b + l]     = -(2.0f * l - 1.0f) * Q[bp + (l - 1)];
        Q[b + l - 1] = -z * Q[b + l];
        #pragma unroll
        for (int m = 0; m <= l - 2; ++m) {
            Q[b + m] = ((2.0f * l - 1.0f) * z * Q[bp + m]
                        - (float)(l + m - 1) * Q[bpp + m])
                       * (1.0f / (float)(l - m));
        }
    }

    float sv[LMAX + 1], cv[LMAX + 1];
    sv[0] = 0.0f; cv[0] = 1.0f;
    #pragma unroll
    for (int m = 1; m <= LMAX; ++m) {
        sv[m] = x * sv[m - 1] + y * cv[m - 1];
        cv[m] = x * cv[m - 1] - y * sv[m - 1];
    }

    const float inv_sqrt2 = 0.70710678118654752440f;
    float* const warp_buf = s_out + warp * (32 * NSH);

    if (p < n) {
        // Row stride 81 words: bank = (17*lane + c) mod 32 is a permutation
        // of lanes at fixed column c (17 odd) -> conflict-free STS.
        float* row = warp_buf + lane * NSH;
        #pragma unroll
        for (int l = 0; l <= LMAX; ++l) {
            const int b  = l * (l + 1) / 2;
            const int cb = l * l;
            #pragma unroll
            for (int k = l; k >= 1; --k)              // m = -l .. -1
                row[cb + l - k] = s_F[b + k] * Q[b + k] * sv[k];
            row[cb + l] = s_F[b] * Q[b] * inv_sqrt2;  // m = 0
            #pragma unroll
            for (int m = 1; m <= l; ++m)              // m = 1 .. l
                row[cb + l + m] = s_F[b + m] * Q[b + m] * cv[m];
        }
    }
    __syncwarp();

    const int valid = min(32, n - chunk_base);
    bool issued_tma = false;

    if (valid == 32) {
        // Order generic-proxy STS ahead of the async-proxy bulk copy.
        asm volatile("fence.proxy.async.shared::cta;" ::: "memory");
        if (lane == 0) {
            uint32_t src = (uint32_t)__cvta_generic_to_shared(warp_buf);
            float* dst   = out + (long long)chunk_base * NSH;
            asm volatile(
                "cp.async.bulk.global.shared::cta.bulk_group [%0], [%1], %2;"
                :: "l"(dst), "r"(src), "n"(CHUNK_BYTES) : "memory");
            asm volatile("cp.async.bulk.commit_group;" ::: "memory");
        }
        issued_tma = true;
    } else if (valid > 0) {
        // Rare tail path: scalar coalesced copy-out.
        const int total = valid * NSH;
        float* dst = out + (long long)chunk_base * NSH;
        for (int i = lane; i < total; i += 32)
            dst[i] = warp_buf[i];
    }

    // Drain the bulk-store group before exit (also guards smem lifetime).
    if (issued_tma && lane == 0)
        asm volatile("cp.async.bulk.wait_group 0;" ::: "memory");
}

extern "C" void kernel_launch(void* const* d_in, const int* in_sizes, int n_in,
                              void* d_out, int out_size)
{
    const float* xyz = (const float*)d_in[0];
    const float* F   = (const float*)d_in[1];
    float* out       = (float*)d_out;
    const int n = in_sizes[0] / 3;
    const int grid = (n + TILE - 1) / TILE;
    sh_kernel<<<grid, TILE>>>(xyz, F, out, n);
}